// round 9
// baseline (speedup 1.0000x reference)
#include <cuda_runtime.h>
#include <cstddef>

// Problem constants (Attention_88811333746876)
#define BB   32
#define HSZ  512
#define CC   256
#define HWN  4096     // 64*64
#define AA   256

#define PX      64           // pixels per tile
#define NBLK    (HWN / PX)   // 64 tiles per batch
#define CHPB    16           // chunks per batch (4 tiles merged per chunk)
#define NCHUNK  (BB * CHPB)  // 512 chunks total

// Scratch (allocation-free rule: __device__ globals)
__device__ float g_whp[8 * BB * AA];          // k-split partials of wh
__device__ float g_v  [BB * CC];
__device__ float g_pctx[NCHUNK * CC];         // 512 KB merged partial contexts
__device__ float g_pm[NCHUNK];                // per-chunk running max
__device__ float g_ps[NCHUNK];                // per-chunk running exp-sum

// ---------------------------------------------------------------------------
// Kernel 1: wh partials. grid (4 a-tiles, 8 k-tiles), 256 thr.
// W_h read exactly once (512 KB, coalesced float4).
// ---------------------------------------------------------------------------
__global__ void k_wh(const float* __restrict__ h_dec,
                     const float* __restrict__ W_h)
{
    __shared__ float Wt[64 * 64];   // [k][a]
    __shared__ float hs[BB * 64];   // [b][k]

    const int a0 = blockIdx.x * 64;
    const int k0 = blockIdx.y * 64;
    const int kp = blockIdx.y;
    const int t  = threadIdx.x;

    {
        const float4* W4 = reinterpret_cast<const float4*>(W_h);
        const int a4 = t & 15, kk = t >> 4;
#pragma unroll
        for (int ii = 0; ii < 4; ++ii) {
            const int k = kk + ii * 16;
            float4 w = W4[(size_t)(k0 + k) * (AA / 4) + (a0 >> 2) + a4];
            reinterpret_cast<float4*>(Wt)[k * 16 + a4] = w;
        }
    }
    {
        const int k = t & 63, bq = t >> 6;
#pragma unroll
        for (int jj = 0; jj < 8; ++jj) {
            const int b = bq + jj * 4;
            hs[b * 64 + k] = h_dec[b * HSZ + k0 + k];
        }
    }
    __syncthreads();

    const int ap2 = t & 31;
    const int bq  = t >> 5;
    float acc[4][2] = {};
#pragma unroll 4
    for (int k = 0; k < 64; ++k) {
        const float w0 = Wt[k * 64 + ap2];
        const float w1 = Wt[k * 64 + ap2 + 32];
#pragma unroll
        for (int i = 0; i < 4; ++i) {
            const float h = hs[(bq * 4 + i) * 64 + k];
            acc[i][0] += h * w0;
            acc[i][1] += h * w1;
        }
    }
#pragma unroll
    for (int i = 0; i < 4; ++i) {
        const int b = bq * 4 + i;
        g_whp[(kp * BB + b) * AA + a0 + ap2]      = acc[i][0];
        g_whp[(kp * BB + b) * AA + a0 + ap2 + 32] = acc[i][1];
    }
}

// ---------------------------------------------------------------------------
// Kernel 2: v[b,c] = sum_a W_fm[c,a] * (sum_kp whp + b_h)[a]
// (b_fm dropped: per-b constant shift -> softmax invariant)
// ---------------------------------------------------------------------------
__global__ void k_v(const float* __restrict__ W_fm,
                    const float* __restrict__ b_h)
{
    const int b    = blockIdx.x;
    const int c    = blockIdx.y * 8 + (threadIdx.x >> 5);
    const int lane = threadIdx.x & 31;

    __shared__ float wh_s[AA];
    if (threadIdx.x < AA) {
        float s = b_h[threadIdx.x];
#pragma unroll
        for (int kp = 0; kp < 8; ++kp)
            s += g_whp[(kp * BB + b) * AA + threadIdx.x];
        wh_s[threadIdx.x] = s;
    }
    __syncthreads();

    const float4* wrow = reinterpret_cast<const float4*>(W_fm + c * AA);
    const float4* whs4 = reinterpret_cast<const float4*>(wh_s);

    float acc = 0.f;
#pragma unroll
    for (int i = 0; i < 2; ++i) {
        const int idx = lane + i * 32;
        float4 wv = wrow[idx];
        float4 hv = whs4[idx];
        acc += wv.x * hv.x + wv.y * hv.y + wv.z * hv.z + wv.w * hv.w;
    }
#pragma unroll
    for (int o = 16; o; o >>= 1) acc += __shfl_xor_sync(0xffffffffu, acc, o);
    if (lane == 0) g_v[b * CC + c] = acc;
}

// ---------------------------------------------------------------------------
// Kernel 3: fused pass with hierarchical online-softmax merge.
// grid (B, 16): CTA (b,cy) owns 4 consecutive 64-px tiles, keeps a running
// (m_run, s_run, acc[channel]) state in registers and merges each tile via
// exact softmax rescaling. Tile data lives in REGISTERS (16 float4/thread);
// only ONE 1-KB pctx row is written per CTA -> 512 KB total, stays in L2.
// ---------------------------------------------------------------------------
__global__ void __launch_bounds__(256, 2) k_fuse(const float* __restrict__ fm)
{
    __shared__ float4 sp4[8 * 16];       // per-warp score partials (2 KB)
    __shared__ float4 sarr4[PX / 4];
    __shared__ float4 e4s [PX / 4];
    __shared__ float  m_sh;
    __shared__ float  ctxp[CC * 17];     // stride-17: conflict-free STS & LDS
    float* s_arr = reinterpret_cast<float*>(sarr4);
    float* e_sh  = reinterpret_cast<float*>(e4s);

    const int b    = blockIdx.x;
    const int cy   = blockIdx.y;         // chunk within batch (0..15)
    const int t    = threadIdx.x;        // 256
    const int pj   = t & 15;             // pixel float4-group (coalescing key)
    const int ch0  = t >> 4;             // channel residue mod 16
    const int wid  = t >> 5;
    const int lane = t & 31;

    const float4* fm4 = reinterpret_cast<const float4*>(fm + (size_t)b * CC * HWN);

    // running merged state (m_run uniform across threads; s_run owned by t0)
    float m_run = -3.0e38f;
    float s_run = 0.f;
    float acc   = 0.f;                   // channel t's merged context partial

    for (int j = 0; j < 4; ++j) {
        const int blk = cy * 4 + j;
        const int p4  = blk * (PX / 4) + pj;

        // ---- load 16 channel-rows into registers (MLP 16) ----
        float4 f[16];
#pragma unroll
        for (int u = 0; u < 16; ++u)
            f[u] = fm4[(ch0 + u * 16) * (HWN / 4) + p4];

        // ---- score partial from registers; v from L2 (1 KB, hot) ----
        float4 part = make_float4(0.f, 0.f, 0.f, 0.f);
#pragma unroll
        for (int u = 0; u < 16; ++u) {
            const float vc = __ldg(&g_v[b * CC + ch0 + u * 16]);
            part.x += f[u].x * vc; part.y += f[u].y * vc;
            part.z += f[u].z * vc; part.w += f[u].w * vc;
        }
        // lanes L and L+16 share pj -> pair-reduce in warp
        part.x += __shfl_xor_sync(0xffffffffu, part.x, 16);
        part.y += __shfl_xor_sync(0xffffffffu, part.y, 16);
        part.z += __shfl_xor_sync(0xffffffffu, part.z, 16);
        part.w += __shfl_xor_sync(0xffffffffu, part.w, 16);

        if (lane < 16) sp4[wid * 16 + pj] = part;
        __syncthreads();                               // B

        if (t < 16) {
            float4 s = sp4[t];
#pragma unroll
            for (int w = 1; w < 8; ++w) {
                float4 x = sp4[w * 16 + t];
                s.x += x.x; s.y += x.y; s.z += x.z; s.w += x.w;
            }
            sarr4[t] = s;
        }
        __syncthreads();                               // C

        if (t < 32) {
            float m = fmaxf(s_arr[t], s_arr[t + 32]);
#pragma unroll
            for (int o = 16; o; o >>= 1)
                m = fmaxf(m, __shfl_xor_sync(0xffffffffu, m, o));
            if (t == 0) m_sh = m;
        }
        __syncthreads();                               // D
        const float Mt = m_sh;                         // tile-local max

        if (t < PX) e_sh[t] = expf(s_arr[t] - Mt);
        __syncthreads();                               // E

        const float4 e4 = e4s[pj];

        // merge scalars (uniform per thread): so = exp(m_run - Mn), sn = exp(Mt - Mn)
        const float Mn = fmaxf(m_run, Mt);
        const float so = expf(m_run - Mt > 0.f ? 0.f : m_run - Mn);
        const float sn = expf(Mt - Mn);

        if (t < 32) {
            float s = e_sh[t] + e_sh[t + 32];
#pragma unroll
            for (int o = 16; o; o >>= 1)
                s += __shfl_xor_sync(0xffffffffu, s, o);
            if (t == 0) s_run = s_run * so + s * sn;
        }

        // ---- ctx partials straight from registers ----
#pragma unroll
        for (int u = 0; u < 16; ++u) {
            const float d = f[u].x * e4.x + f[u].y * e4.y
                          + f[u].z * e4.z + f[u].w * e4.w;
            ctxp[(ch0 + u * 16) * 17 + pj] = d;
        }
        __syncthreads();                               // F

        {
            float d = 0.f;
#pragma unroll
            for (int q = 0; q < 16; ++q) d += ctxp[t * 17 + q];
            acc = acc * so + d * sn;
        }
        m_run = Mn;
        // no trailing barrier: next iter's barrier B fences sp4/ctxp reuse
    }

    const int chunk = b * CHPB + cy;
    if (t == 0) { g_pm[chunk] = m_run; g_ps[chunk] = s_run; }
    g_pctx[(size_t)chunk * CC + t] = acc;              // coalesced 1 KB
}

// ---------------------------------------------------------------------------
// Kernel 4: final exact-softmax combine over 16 chunks per batch.
// grid B, 256 thr. All data (512 KB + stats) written at tail of k_fuse ->
// L2-resident. 16 unrolled L2-hit loads per thread, minimal prologue.
// ---------------------------------------------------------------------------
__global__ void k_combine(float* __restrict__ out)
{
    const int b = blockIdx.x;
    const int t = threadIdx.x;             // 256

    __shared__ float w_s[CHPB];
    __shared__ float inv_sh;

    if (t < CHPB) {
        const float m0 = g_pm[b * CHPB + t];
        float m = m0;
#pragma unroll
        for (int o = 8; o; o >>= 1)
            m = fmaxf(m, __shfl_xor_sync(0x0000ffffu, m, o));
        const float w = expf(m0 - m);      // m = global max (uniform lanes 0-15)
        w_s[t] = w;
        float d = g_ps[b * CHPB + t] * w;
#pragma unroll
        for (int o = 8; o; o >>= 1)
            d += __shfl_xor_sync(0x0000ffffu, d, o);
        if (t == 0) inv_sh = 1.f / d;
    }
    __syncthreads();
    const float inv = inv_sh;

    float acc = 0.f;
#pragma unroll
    for (int j = 0; j < CHPB; ++j)
        acc += g_pctx[(size_t)(b * CHPB + j) * CC + t] * w_s[j];

    out[b * CC + t] = acc * inv;
}

// ---------------------------------------------------------------------------
// Launch
// ---------------------------------------------------------------------------
extern "C" void kernel_launch(void* const* d_in, const int* in_sizes, int n_in,
                              void* d_out, int out_size)
{
    const float* h_dec = nullptr;
    const float* fm    = nullptr;
    const float* W_fm  = nullptr;
    const float* W_h   = nullptr;
    const float* b_h   = nullptr;
    const float* biases[2] = {nullptr, nullptr};
    int nb = 0;

    for (int i = 0; i < n_in; ++i) {
        switch (in_sizes[i]) {
            case BB * HSZ:      h_dec = (const float*)d_in[i]; break;   // 16384
            case BB * CC * HWN: fm    = (const float*)d_in[i]; break;   // 33554432
            case CC * AA:       W_fm  = (const float*)d_in[i]; break;   // 65536
            case HSZ * AA:      W_h   = (const float*)d_in[i]; break;   // 131072
            case AA:            if (nb < 2) biases[nb++] = (const float*)d_in[i]; break;
            default: break;
        }
    }
    b_h = biases[1];   // metadata order: b_fm first (unused), b_h second

    float* out = (float*)d_out;

    k_wh     <<<dim3(4, 8),       256>>>(h_dec, W_h);
    k_v      <<<dim3(BB, CC / 8), 256>>>(W_fm, b_h);
    k_fuse   <<<dim3(BB, CHPB),   256>>>(fm);
    k_combine<<<BB,               256>>>(out);
}